// round 1
// baseline (speedup 1.0000x reference)
#include <cuda_runtime.h>
#include <math.h>

// ChamferLoss: batch=64, k=2048 2-D points (freqs = cols [0,2048), amps = cols [2048,4096))
// result = mean_b [ mean_i min_j d(p_i,t_j) + mean_j min_i d(p_i,t_j) ]

#define K        2048
#define BATCH    64
#define THREADS  256
#define ROWS     8          // rows per thread: 256*8 = 2048
#define NBLOCKS  (2 * BATCH) // one block per (batch, direction)

__device__ float g_partials[NBLOCKS];

__global__ __launch_bounds__(THREADS, 1)
void chamfer_pass_kernel(const float* __restrict__ pred,
                         const float* __restrict__ targ)
{
    const int bx    = blockIdx.x;
    const int batch = bx >> 1;
    const int dir   = bx & 1;

    // dir 0: for each predicted point, min over targets  (min over axis=2 term)
    // dir 1: for each target point, min over predicted   (min over axis=1 term)
    const float* row_base = (dir == 0 ? pred : targ) + batch * (2 * K);
    const float* col_base = (dir == 0 ? targ : pred) + batch * (2 * K);

    __shared__ float4 sh[K];          // (x, y, x^2+y^2, 0) per column point — 32 KB

    const int tid = threadIdx.x;

    // Cooperative load of column points into shared (coalesced on both halves)
    #pragma unroll
    for (int r = 0; r < ROWS; ++r) {
        int j = r * THREADS + tid;
        float x = col_base[j];
        float y = col_base[j + K];
        sh[j] = make_float4(x, y, fmaf(x, x, y * y), 0.0f);
    }
    __syncthreads();

    // Register tile: 8 row-points per thread
    float ax[ROWS], ay[ROWS], p2[ROWS], mn[ROWS];
    #pragma unroll
    for (int r = 0; r < ROWS; ++r) {
        int i = r * THREADS + tid;
        float x = row_base[i];
        float y = row_base[i + K];
        ax[r] = -2.0f * x;
        ay[r] = -2.0f * y;
        p2[r] = fmaf(x, x, y * y);
        mn[r] = INFINITY;
    }

    // Main loop: v = t2 - 2*px*tx - 2*py*ty  (row-constant p2 folded out of the min)
    // 1 LDS.128 broadcast + 16 FFMA + 8 FMNMX per j per warp.
    #pragma unroll 4
    for (int j = 0; j < K; ++j) {
        float4 t = sh[j];
        #pragma unroll
        for (int r = 0; r < ROWS; ++r) {
            float v = fmaf(ax[r], t.x, fmaf(ay[r], t.y, t.z));
            mn[r] = fminf(mn[r], v);
        }
    }

    // Per-thread sum of sqrt(min d^2)
    float s = 0.0f;
    #pragma unroll
    for (int r = 0; r < ROWS; ++r)
        s += sqrtf(fmaxf(p2[r] + mn[r], 0.0f));

    // Block reduction (deterministic fixed order)
    __shared__ float red[THREADS];
    red[tid] = s;
    __syncthreads();
    #pragma unroll
    for (int off = THREADS / 2; off >= 32; off >>= 1) {
        if (tid < off) red[tid] += red[tid + off];
        __syncthreads();
    }
    if (tid < 32) {
        float v = red[tid];
        #pragma unroll
        for (int off = 16; off > 0; off >>= 1)
            v += __shfl_down_sync(0xFFFFFFFF, v, off);
        if (tid == 0) g_partials[bx] = v;
    }
}

__global__ void chamfer_finalize_kernel(float* __restrict__ out)
{
    // Single warp: deterministic sum of 128 partials, then scale by 1/(K*BATCH)
    int lane = threadIdx.x;
    float v = 0.0f;
    #pragma unroll
    for (int i = 0; i < NBLOCKS / 32; ++i)
        v += g_partials[i * 32 + lane];
    #pragma unroll
    for (int off = 16; off > 0; off >>= 1)
        v += __shfl_down_sync(0xFFFFFFFF, v, off);
    if (lane == 0)
        out[0] = v * (1.0f / ((float)K * (float)BATCH));
}

extern "C" void kernel_launch(void* const* d_in, const int* in_sizes, int n_in,
                              void* d_out, int out_size)
{
    const float* pred = (const float*)d_in[0];
    const float* targ = (const float*)d_in[1];
    float* out = (float*)d_out;

    chamfer_pass_kernel<<<NBLOCKS, THREADS>>>(pred, targ);
    chamfer_finalize_kernel<<<1, 32>>>(out);
}

// round 2
// speedup vs baseline: 1.0124x; 1.0124x over previous
#include <cuda_runtime.h>
#include <math.h>
#include <stdint.h>

// ChamferLoss: batch=64, k=2048 2-D points (freqs = cols [0,2048), amps = cols [2048,4096))
// result = mean_b [ mean_i min_j d(p_i,t_j) + mean_j min_i d(p_i,t_j) ]
//
// Per pair: d^2(i,j) = p2_i + (t2_j - 2 p_i . t_j). The row-constant p2_i is folded
// out of the min (sqrt/min are monotone), so the inner body is a 2-term FMA chain + min.
// FMA chain runs as packed fma.rn.f32x2 (FFMA2) over row-pairs — a 2x fma-pipe win
// ptxas cannot produce from C++. Column points are stored in shared pre-duplicated
// as (tx,tx,ty,ty) + (tz,tz) so packed operands come straight out of LDS with no MOVs.

#define K        2048
#define BATCH    64
#define THREADS  256
#define ROWS     8            // rows per thread: 256*8 = 2048
#define NBLOCKS  (2 * BATCH)  // one block per (batch, direction)

__device__ float g_partials[NBLOCKS];

__device__ __forceinline__ uint32_t smem_u32(const void* p) {
    uint32_t a;
    asm("{ .reg .u64 t; cvta.to.shared.u64 t, %1; cvt.u32.u64 %0, t; }"
        : "=r"(a) : "l"(p));
    return a;
}

__global__ __launch_bounds__(THREADS, 1)
void chamfer_pass_kernel(const float* __restrict__ pred,
                         const float* __restrict__ targ)
{
    const int bx    = blockIdx.x;
    const int batch = bx >> 1;
    const int dir   = bx & 1;

    const float* row_base = (dir == 0 ? pred : targ) + batch * (2 * K);
    const float* col_base = (dir == 0 ? targ : pred) + batch * (2 * K);

    __shared__ float4 sh_xy[K];   // (tx,tx,ty,ty)  — 32 KB
    __shared__ float2 sh_z [K];   // (tz,tz)        — 16 KB

    const int tid = threadIdx.x;

    // Cooperative load of column points (coalesced on both halves), pre-duplicated.
    #pragma unroll
    for (int r = 0; r < ROWS; ++r) {
        int j = r * THREADS + tid;
        float x = col_base[j];
        float y = col_base[j + K];
        sh_xy[j] = make_float4(x, x, y, y);
        float z = fmaf(x, x, y * y);
        sh_z[j]  = make_float2(z, z);
    }
    __syncthreads();

    // Register tile: 8 row-points per thread, constants packed per row-pair.
    uint64_t axp[ROWS / 2], ayp[ROWS / 2];
    float p2[ROWS], mn[ROWS];
    #pragma unroll
    for (int p = 0; p < ROWS / 2; ++p) {
        int i0 = (2 * p)     * THREADS + tid;
        int i1 = (2 * p + 1) * THREADS + tid;
        float x0 = row_base[i0], y0 = row_base[i0 + K];
        float x1 = row_base[i1], y1 = row_base[i1 + K];
        float ax0 = -2.0f * x0, ax1 = -2.0f * x1;
        float ay0 = -2.0f * y0, ay1 = -2.0f * y1;
        asm("mov.b64 %0, {%1, %2};" : "=l"(axp[p]) : "f"(ax0), "f"(ax1));
        asm("mov.b64 %0, {%1, %2};" : "=l"(ayp[p]) : "f"(ay0), "f"(ay1));
        p2[2 * p]     = fmaf(x0, x0, y0 * y0);
        p2[2 * p + 1] = fmaf(x1, x1, y1 * y1);
        mn[2 * p]     = INFINITY;
        mn[2 * p + 1] = INFINITY;
    }

    uint32_t addr_xy = smem_u32(sh_xy);
    uint32_t addr_z  = smem_u32(sh_z);

    // Main loop: per j per thread = 2 LDS + 4 FFMA2 + 8 FMNMX.
    #pragma unroll 4
    for (int j = 0; j < K; ++j) {
        uint64_t txtx, tyty, tztz;
        asm("ld.shared.v2.b64 {%0, %1}, [%2];"
            : "=l"(txtx), "=l"(tyty) : "r"(addr_xy + j * 16));
        asm("ld.shared.b64 %0, [%1];"
            : "=l"(tztz) : "r"(addr_z + j * 8));

        #pragma unroll
        for (int p = 0; p < ROWS / 2; ++p) {
            uint64_t acc, v;
            asm("fma.rn.f32x2 %0, %1, %2, %3;"
                : "=l"(acc) : "l"(ayp[p]), "l"(tyty), "l"(tztz));
            asm("fma.rn.f32x2 %0, %1, %2, %3;"
                : "=l"(v) : "l"(axp[p]), "l"(txtx), "l"(acc));
            float vlo, vhi;
            asm("mov.b64 {%0, %1}, %2;" : "=f"(vlo), "=f"(vhi) : "l"(v));
            mn[2 * p]     = fminf(mn[2 * p],     vlo);
            mn[2 * p + 1] = fminf(mn[2 * p + 1], vhi);
        }
    }

    // Per-thread sum of sqrt(min d^2) (re-add the folded p2 term).
    float s = 0.0f;
    #pragma unroll
    for (int r = 0; r < ROWS; ++r)
        s += sqrtf(fmaxf(p2[r] + mn[r], 0.0f));

    // Block reduction (deterministic fixed order); reuse sh_xy as scratch.
    __syncthreads();
    float* red = (float*)sh_xy;
    red[tid] = s;
    __syncthreads();
    #pragma unroll
    for (int off = THREADS / 2; off >= 32; off >>= 1) {
        if (tid < off) red[tid] += red[tid + off];
        __syncthreads();
    }
    if (tid < 32) {
        float v = red[tid];
        #pragma unroll
        for (int off = 16; off > 0; off >>= 1)
            v += __shfl_down_sync(0xFFFFFFFF, v, off);
        if (tid == 0) g_partials[bx] = v;
    }
}

__global__ void chamfer_finalize_kernel(float* __restrict__ out)
{
    int lane = threadIdx.x;
    float v = 0.0f;
    #pragma unroll
    for (int i = 0; i < NBLOCKS / 32; ++i)
        v += g_partials[i * 32 + lane];
    #pragma unroll
    for (int off = 16; off > 0; off >>= 1)
        v += __shfl_down_sync(0xFFFFFFFF, v, off);
    if (lane == 0)
        out[0] = v * (1.0f / ((float)K * (float)BATCH));
}

extern "C" void kernel_launch(void* const* d_in, const int* in_sizes, int n_in,
                              void* d_out, int out_size)
{
    const float* pred = (const float*)d_in[0];
    const float* targ = (const float*)d_in[1];
    float* out = (float*)d_out;

    chamfer_pass_kernel<<<NBLOCKS, THREADS>>>(pred, targ);
    chamfer_finalize_kernel<<<1, 32>>>(out);
}